// round 15
// baseline (speedup 1.0000x reference)
#include <cuda_runtime.h>
#include <cstdint>

// Problem: B=4, S=4096, H=16, Dk=Dv=64.  out = 0.95*M + sum_rows w*k v^T per head.
#define H_     16
#define DK_    64
#define DV_    64
#define HD_    1024           // floats per (b,s) row = H*64
#define DECAY_ 0.95f
#define NBLK_  296            // 148*2 -> exactly one wave at occupancy 2

// bf16x2 planes, double buffered. Word addr: buf*BUFW + PLANE + pair*72 + col.
// pair = k-row-pair (0..31), col = m or n (0..63). Stride 72 => fragment LDS
// banks (8*c2 + r2) % 32 -> conflict-free.
#define KHI_  0
#define KLO_  2304
#define VHI_  4608
#define VLO_  6912
#define BUFW_ 9216
#define SMEM_BYTES (2 * BUFW_ * 4)   // 73728

// hi = bf16x2{lo-half=bf16(x0), hi-half=bf16(x1)}; lo = bf16x2 of residuals
__device__ __forceinline__ void split2(float x0, float x1, uint32_t& hi, uint32_t& lo) {
    asm("cvt.rn.bf16x2.f32 %0, %1, %2;" : "=r"(hi) : "f"(x1), "f"(x0));
    float h0 = __uint_as_float(hi << 16);
    float h1 = __uint_as_float(hi & 0xffff0000u);
    float l0 = x0 - h0;
    float l1 = x1 - h1;
    asm("cvt.rn.bf16x2.f32 %0, %1, %2;" : "=r"(lo) : "f"(l1), "f"(l0));
}

__device__ __forceinline__ void mma16816(float* c, const uint32_t* a,
                                         uint32_t b0, uint32_t b1) {
    asm volatile(
        "mma.sync.aligned.m16n8k16.row.col.f32.bf16.bf16.f32 "
        "{%0,%1,%2,%3}, {%4,%5,%6,%7}, {%8,%9}, {%0,%1,%2,%3};"
        : "+f"(c[0]), "+f"(c[1]), "+f"(c[2]), "+f"(c[3])
        : "r"(a[0]), "r"(a[1]), "r"(a[2]), "r"(a[3]), "r"(b0), "r"(b1));
}

// Fill ownership: thread (kpp = tid>>4, segq = tid&15) stages rows
// 4*kpp..4*kpp+3, cols 4*segq..4*segq+3.  LDG: 16 lanes x 16B = 256B/row.
#define LOAD_STAGE(stg)                                                        \
    do {                                                                       \
        const int r0_ = (stg) * 64 + 4 * kpp;                                  \
        const float* kp_ = kbase + (size_t)r0_ * HD_ + 4 * segq;               \
        const float* vp_ = vbase + (size_t)r0_ * HD_ + 4 * segq;               \
        sk[0] = *(const float4*)(kp_);                                         \
        sk[1] = *(const float4*)(kp_ + HD_);                                   \
        sk[2] = *(const float4*)(kp_ + 2 * HD_);                               \
        sk[3] = *(const float4*)(kp_ + 3 * HD_);                               \
        sv[0] = *(const float4*)(vp_);                                         \
        sv[1] = *(const float4*)(vp_ + HD_);                                   \
        sv[2] = *(const float4*)(vp_ + 2 * HD_);                               \
        sv[3] = *(const float4*)(vp_ + 3 * HD_);                               \
        w4 = *(const float4*)(ws + r0_);                                       \
    } while (0)

// Split in regs, store bf16x2 planes. Each STS.128 phase covers a contiguous
// 128B (banks 4*segq..+3 distinct across segq 0..7) -> conflict-free.
#define STORE_STAGE(b)                                                         \
    do {                                                                       \
        uint32_t* pb_ = pl + (b) * BUFW_;                                      \
        const float wf_[4] = {w4.x, w4.y, w4.z, w4.w};                         \
        _Pragma("unroll")                                                      \
        for (int d = 0; d < 2; ++d) {                                          \
            const float* A_  = &sk[2 * d].x;                                   \
            const float* B_  = &sk[2 * d + 1].x;                               \
            const float* VA_ = &sv[2 * d].x;                                   \
            const float* VB_ = &sv[2 * d + 1].x;                               \
            uint32_t kh[4], kl[4], vh[4], vl[4];                               \
            _Pragma("unroll")                                                  \
            for (int j = 0; j < 4; ++j) {                                      \
                split2(A_[j], B_[j], kh[j], kl[j]);                            \
                split2(VA_[j] * wf_[2 * d], VB_[j] * wf_[2 * d + 1],           \
                       vh[j], vl[j]);                                          \
            }                                                                  \
            const uint32_t wb_ = (uint32_t)((2 * kpp + d) * 72 + 4 * segq);    \
            *(uint4*)(pb_ + KHI_ + wb_) = make_uint4(kh[0], kh[1], kh[2], kh[3]); \
            *(uint4*)(pb_ + KLO_ + wb_) = make_uint4(kl[0], kl[1], kl[2], kl[3]); \
            *(uint4*)(pb_ + VHI_ + wb_) = make_uint4(vh[0], vh[1], vh[2], vh[3]); \
            *(uint4*)(pb_ + VLO_ + wb_) = make_uint4(vl[0], vl[1], vl[2], vl[3]); \
        }                                                                      \
    } while (0)

__global__ __launch_bounds__(256, 2)
void l1w_main_kernel(const float* __restrict__ keys,
                     const float* __restrict__ values,
                     const float* __restrict__ ws,
                     float* __restrict__ out) {
    extern __shared__ __align__(16) uint32_t pl[];

    const int tid  = threadIdx.x;
    const int wid  = tid >> 5;
    const int lane = tid & 31;
    const int bid  = blockIdx.x;

    // bid -> (head h, first stage s0, stage count nt); 256 stages of 64 rows/head.
    int h, nt, s0;
    if (bid < 152) {                        // heads 0..7: 19 blocks each
        h = bid / 19;
        const int ci = bid - 19 * h;
        if (ci < 9) { nt = 14; s0 = 14 * ci; }
        else        { nt = 13; s0 = 126 + 13 * (ci - 9); }
    } else {                                // heads 8..15: 18 blocks each
        const int r = bid - 152;
        h = 8 + r / 18;
        const int ci = r - 18 * (h - 8);
        if (ci < 4) { nt = 15; s0 = 15 * ci; }
        else        { nt = 14; s0 = 60 + 14 * (ci - 4); }
    }

    const float* kbase = keys   + (size_t)h * DK_;
    const float* vbase = values + (size_t)h * DV_;

    // fill mapping
    const int kpp  = tid >> 4;
    const int segq = tid & 15;
    // MMA mapping: 8 warps = 2 k-groups x (2m x 2n); warp tile 32m x 32n over
    // 2 k-steps. k-groups combined through smem at the end.
    const int wg = wid >> 2;
    const int wm = wid & 1;
    const int wn = (wid >> 1) & 1;
    const int r2 = lane >> 2;
    const int c2 = lane & 3;

    float cacc[2][4][4];
#pragma unroll
    for (int mt = 0; mt < 2; ++mt)
#pragma unroll
        for (int n2 = 0; n2 < 4; ++n2)
#pragma unroll
            for (int i = 0; i < 4; ++i) cacc[mt][n2][i] = 0.0f;

    float4 sk[4], sv[4], w4;

    LOAD_STAGE(s0);
    STORE_STAGE(0);
    __syncthreads();

    for (int s = 0; s < nt; ++s) {
        if (s + 1 < nt) LOAD_STAGE(s0 + s + 1);   // LDGs in flight under MMAs

        // ---- MMA phase from buffer s&1: this warp's 2 k-steps ----
        {
            const uint32_t* sm = pl + (s & 1) * BUFW_;
#pragma unroll
            for (int ss = 0; ss < 2; ++ss) {
                const int st = 2 * wg + ss;
                const uint32_t kro = (uint32_t)((8 * st + c2) * 72);
                uint32_t aH[2][4], aL[2][4];
#pragma unroll
                for (int mt = 0; mt < 2; ++mt) {
                    const uint32_t cc = (uint32_t)(32 * wm + 16 * mt + r2);
                    aH[mt][0] = sm[KHI_ + kro + cc];
                    aH[mt][1] = sm[KHI_ + kro + cc + 8];
                    aH[mt][2] = sm[KHI_ + kro + 288 + cc];
                    aH[mt][3] = sm[KHI_ + kro + 288 + cc + 8];
                    aL[mt][0] = sm[KLO_ + kro + cc];
                    aL[mt][1] = sm[KLO_ + kro + cc + 8];
                    aL[mt][2] = sm[KLO_ + kro + 288 + cc];
                    aL[mt][3] = sm[KLO_ + kro + 288 + cc + 8];
                }
#pragma unroll
                for (int n2 = 0; n2 < 4; ++n2) {
                    const uint32_t nn = (uint32_t)(32 * wn + 8 * n2 + r2);
                    const uint32_t bH0 = sm[VHI_ + kro + nn];
                    const uint32_t bH1 = sm[VHI_ + kro + 288 + nn];
                    const uint32_t bL0 = sm[VLO_ + kro + nn];
                    const uint32_t bL1 = sm[VLO_ + kro + 288 + nn];
#pragma unroll
                    for (int mt = 0; mt < 2; ++mt) {
                        mma16816(cacc[mt][n2], aH[mt], bH0, bH1);
                        mma16816(cacc[mt][n2], aH[mt], bL0, bL1);
                        mma16816(cacc[mt][n2], aL[mt], bH0, bH1);
                    }
                }
            }
        }

        if (s + 1 < nt) STORE_STAGE((s + 1) & 1);
        __syncthreads();
    }

    // ---- combine k-groups via smem, then RED.ADD into pre-decayed out ----
    float* scr = (float*)pl;               // 64 x 68 fp32 scratch (reuses planes)
    if (wg == 1) {
#pragma unroll
        for (int mt = 0; mt < 2; ++mt)
#pragma unroll
            for (int n2 = 0; n2 < 4; ++n2) {
                const int row = 32 * wm + 16 * mt + r2;
                const int col = 32 * wn + 8 * n2 + 2 * c2;
                scr[row * 68 + col]           = cacc[mt][n2][0];
                scr[row * 68 + col + 1]       = cacc[mt][n2][1];
                scr[(row + 8) * 68 + col]     = cacc[mt][n2][2];
                scr[(row + 8) * 68 + col + 1] = cacc[mt][n2][3];
            }
    }
    __syncthreads();
    if (wg == 0) {
        float* outp = out + ((size_t)h << 12);
#pragma unroll
        for (int mt = 0; mt < 2; ++mt)
#pragma unroll
            for (int n2 = 0; n2 < 4; ++n2) {
                const int row = 32 * wm + 16 * mt + r2;
                const int col = 32 * wn + 8 * n2 + 2 * c2;
                atomicAdd(outp + (size_t)row * DV_ + col,
                          cacc[mt][n2][0] + scr[row * 68 + col]);
                atomicAdd(outp + (size_t)row * DV_ + col + 1,
                          cacc[mt][n2][1] + scr[row * 68 + col + 1]);
                atomicAdd(outp + (size_t)(row + 8) * DV_ + col,
                          cacc[mt][n2][2] + scr[(row + 8) * 68 + col]);
                atomicAdd(outp + (size_t)(row + 8) * DV_ + col + 1,
                          cacc[mt][n2][3] + scr[(row + 8) * 68 + col + 1]);
            }
    }
}

__global__ void l1w_init_kernel(const float* __restrict__ memory,
                                float* __restrict__ out) {
    const int e4 = blockIdx.x * blockDim.x + threadIdx.x;  // 0..16383 float4
    float4 m = ((const float4*)memory)[e4];
    m.x *= DECAY_; m.y *= DECAY_; m.z *= DECAY_; m.w *= DECAY_;
    ((float4*)out)[e4] = m;
}

extern "C" void kernel_launch(void* const* d_in, const int* in_sizes, int n_in,
                              void* d_out, int out_size) {
    const float* memory = (const float*)d_in[0];   // (16,64,64)
    const float* keys   = (const float*)d_in[1];   // (4,4096,16,64)
    const float* values = (const float*)d_in[2];   // (4,4096,16,64)
    const float* ws     = (const float*)d_in[3];   // (4,4096)
    float* out = (float*)d_out;                    // (16,64,64)

    cudaFuncSetAttribute(l1w_main_kernel,
                         cudaFuncAttributeMaxDynamicSharedMemorySize,
                         SMEM_BYTES);

    l1w_init_kernel<<<128, 128>>>(memory, out);
    l1w_main_kernel<<<NBLK_, 256, SMEM_BYTES>>>(keys, values, ws, out);
}

// round 16
// speedup vs baseline: 1.2896x; 1.2896x over previous
#include <cuda_runtime.h>
#include <cstdint>

// Problem: B=4, S=4096, H=16, Dk=Dv=64.  out = 0.95*M + sum_rows w*k v^T per head.
#define H_     16
#define DK_    64
#define DV_    64
#define HD_    1024           // floats per (b,s) row = H*64
#define DECAY_ 0.95f
#define NBLK_  444            // 148*3 -> exactly one wave at occupancy 3

// Raw fp32 smem planes per buffer: K[k][m], V[k][n], k=0..63, row stride 68 floats.
// Bank of element (k,m) = (4k + m) % 32 -> fragment LDS conflict-free (8c2+r2 distinct).
#define KSTR_   68
#define PLANEF_ (64 * KSTR_)        // 4352 floats
#define BUFF_   (2 * PLANEF_ + 64)  // + 64 w floats = 8768 floats
#define BUFB_   35072               // bytes per buffer
#define VOFF_B_ 17408               // V plane byte offset
#define WOFF_B_ 34816               // w byte offset

// hi = bf16x2{lo-half=bf16(x0), hi-half=bf16(x1)}; lo = bf16x2 of residuals
__device__ __forceinline__ void split2(float x0, float x1, uint32_t& hi, uint32_t& lo) {
    asm("cvt.rn.bf16x2.f32 %0, %1, %2;" : "=r"(hi) : "f"(x1), "f"(x0));
    float h0 = __uint_as_float(hi << 16);
    float h1 = __uint_as_float(hi & 0xffff0000u);
    float l0 = x0 - h0;
    float l1 = x1 - h1;
    asm("cvt.rn.bf16x2.f32 %0, %1, %2;" : "=r"(lo) : "f"(l1), "f"(l0));
}

__device__ __forceinline__ void mma16816(float* c, const uint32_t* a,
                                         uint32_t b0, uint32_t b1) {
    asm volatile(
        "mma.sync.aligned.m16n8k16.row.col.f32.bf16.bf16.f32 "
        "{%0,%1,%2,%3}, {%4,%5,%6,%7}, {%8,%9}, {%0,%1,%2,%3};"
        : "+f"(c[0]), "+f"(c[1]), "+f"(c[2]), "+f"(c[3])
        : "r"(a[0]), "r"(a[1]), "r"(a[2]), "r"(a[3]), "r"(b0), "r"(b1));
}

__device__ __forceinline__ void cp16(uint32_t dst, const float* src) {
    asm volatile("cp.async.cg.shared.global [%0], [%1], 16;" :: "r"(dst), "l"(src));
}

// Issue all cp.asyncs for one 64-row stage into buffer b, then commit the group.
#define ISSUE_STAGE(stg, b)                                                    \
    do {                                                                       \
        const int row0_ = (stg) * 64;                                          \
        const uint32_t bb_ = sbase + (uint32_t)(b) * BUFB_;                    \
        _Pragma("unroll")                                                      \
        for (int i = 0; i < 8; ++i) {                                          \
            const int idx = i * 128 + tid;                                     \
            const int row = idx >> 4;                                          \
            const int seg = idx & 15;                                          \
            const uint32_t d = (uint32_t)(row * 272 + seg * 16);               \
            const size_t g = (size_t)(row0_ + row) * HD_ + seg * 4;            \
            cp16(bb_ + d, kbase + g);                                          \
            cp16(bb_ + VOFF_B_ + d, vbase + g);                                \
        }                                                                      \
        if (tid < 16) cp16(bb_ + WOFF_B_ + tid * 16, ws + row0_ + tid * 4);    \
        asm volatile("cp.async.commit_group;" ::: "memory");                   \
    } while (0)

__global__ __launch_bounds__(128, 3)
void l1w_main_kernel(const float* __restrict__ keys,
                     const float* __restrict__ values,
                     const float* __restrict__ ws,
                     float* __restrict__ out) {
    extern __shared__ __align__(16) float dsm[];
    uint32_t sbase;
    asm("{ .reg .u64 t; cvta.to.shared.u64 t, %1; cvt.u32.u64 %0, t; }"
        : "=r"(sbase) : "l"(dsm));

    const int tid  = threadIdx.x;
    const int wid  = tid >> 5;
    const int lane = tid & 31;
    const int bid  = blockIdx.x;

    // bid -> (head h, first stage s0, stage count nt); 256 stages of 64 rows per head.
    int h, nt, s0;
    if (bid < 336) {                       // heads 0..11: 28 chunks each
        h = bid / 28;
        const int ci = bid - 28 * h;
        if (ci < 4) { nt = 10; s0 = 10 * ci; }
        else        { nt = 9;  s0 = 40 + 9 * (ci - 4); }
    } else {                               // heads 12..15: 27 chunks each
        const int r = bid - 336;
        h = 12 + r / 27;
        const int ci = r - 27 * (h - 12);
        if (ci < 13) { nt = 10; s0 = 10 * ci; }
        else         { nt = 9;  s0 = 130 + 9 * (ci - 13); }
    }

    const float* kbase = keys   + (size_t)h * DK_;
    const float* vbase = values + (size_t)h * DV_;

    // Warp tiling 2m x 2n: warp covers rows 32*wm..+31, cols 32*wn..+31.
    const int wm = wid & 1;
    const int wn = wid >> 1;
    const int r2 = lane >> 2;
    const int c2 = lane & 3;

    float cacc[2][4][4];
#pragma unroll
    for (int mt = 0; mt < 2; ++mt)
#pragma unroll
        for (int n2 = 0; n2 < 4; ++n2)
#pragma unroll
            for (int i = 0; i < 4; ++i) cacc[mt][n2][i] = 0.0f;

    ISSUE_STAGE(s0, 0);

    for (int s = 0; s < nt; ++s) {
        if (s + 1 < nt) {
            ISSUE_STAGE(s0 + s + 1, (s + 1) & 1);
            asm volatile("cp.async.wait_group 1;" ::: "memory");
        } else {
            asm volatile("cp.async.wait_group 0;" ::: "memory");
        }
        __syncthreads();                         // stage s visible to all warps

        const float* Kp = dsm + (s & 1) * BUFF_;
        const float* Vp = Kp + PLANEF_;
        const float* Wp = Vp + PLANEF_;

#pragma unroll
        for (int st = 0; st < 4; ++st) {
            const int k0 = 16 * st + 2 * c2;
            const float w00 = Wp[k0],     w01 = Wp[k0 + 1];
            const float w10 = Wp[k0 + 8], w11 = Wp[k0 + 9];

            uint32_t bH[4][2], bL[4][2];
#pragma unroll
            for (int n2 = 0; n2 < 4; ++n2) {
                const int n = 32 * wn + 8 * n2 + r2;
                split2(Vp[k0 * KSTR_ + n] * w00,
                       Vp[(k0 + 1) * KSTR_ + n] * w01, bH[n2][0], bL[n2][0]);
                split2(Vp[(k0 + 8) * KSTR_ + n] * w10,
                       Vp[(k0 + 9) * KSTR_ + n] * w11, bH[n2][1], bL[n2][1]);
            }
#pragma unroll
            for (int mt = 0; mt < 2; ++mt) {
                const int m = 32 * wm + 16 * mt + r2;
                uint32_t aH[4], aL[4];
                split2(Kp[k0 * KSTR_ + m],
                       Kp[(k0 + 1) * KSTR_ + m],     aH[0], aL[0]);
                split2(Kp[k0 * KSTR_ + m + 8],
                       Kp[(k0 + 1) * KSTR_ + m + 8], aH[1], aL[1]);
                split2(Kp[(k0 + 8) * KSTR_ + m],
                       Kp[(k0 + 9) * KSTR_ + m],     aH[2], aL[2]);
                split2(Kp[(k0 + 8) * KSTR_ + m + 8],
                       Kp[(k0 + 9) * KSTR_ + m + 8], aH[3], aL[3]);
#pragma unroll
                for (int n2 = 0; n2 < 4; ++n2) {
                    mma16816(cacc[mt][n2], aH, bH[n2][0], bH[n2][1]);
                    mma16816(cacc[mt][n2], aH, bL[n2][0], bL[n2][1]);
                    mma16816(cacc[mt][n2], aL, bH[n2][0], bH[n2][1]);
                }
            }
        }
        __syncthreads();                         // buffer s&1 free for reuse
    }

    // ---- epilogue: RED.ADD the per-block partials into out (pre-decayed) ----
    float* outp = out + ((size_t)h << 12);
#pragma unroll
    for (int mt = 0; mt < 2; ++mt)
#pragma unroll
        for (int n2 = 0; n2 < 4; ++n2) {
            const int row = 32 * wm + 16 * mt + r2;
            const int col = 32 * wn + 8 * n2 + 2 * c2;
            atomicAdd(outp + (size_t)row * DV_ + col,           cacc[mt][n2][0]);
            atomicAdd(outp + (size_t)row * DV_ + col + 1,       cacc[mt][n2][1]);
            atomicAdd(outp + (size_t)(row + 8) * DV_ + col,     cacc[mt][n2][2]);
            atomicAdd(outp + (size_t)(row + 8) * DV_ + col + 1, cacc[mt][n2][3]);
        }
}

__global__ void l1w_init_kernel(const float* __restrict__ memory,
                                float* __restrict__ out) {
    const int e4 = blockIdx.x * blockDim.x + threadIdx.x;  // 0..16383 float4
    float4 m = ((const float4*)memory)[e4];
    m.x *= DECAY_; m.y *= DECAY_; m.z *= DECAY_; m.w *= DECAY_;
    ((float4*)out)[e4] = m;
}

extern "C" void kernel_launch(void* const* d_in, const int* in_sizes, int n_in,
                              void* d_out, int out_size) {
    const float* memory = (const float*)d_in[0];   // (16,64,64)
    const float* keys   = (const float*)d_in[1];   // (4,4096,16,64)
    const float* values = (const float*)d_in[2];   // (4,4096,16,64)
    const float* ws     = (const float*)d_in[3];   // (4,4096)
    float* out = (float*)d_out;                    // (16,64,64)

    cudaFuncSetAttribute(l1w_main_kernel,
                         cudaFuncAttributeMaxDynamicSharedMemorySize,
                         2 * BUFB_);

    l1w_init_kernel<<<128, 128>>>(memory, out);
    l1w_main_kernel<<<NBLK_, 128, 2 * BUFB_>>>(keys, values, ws, out);
}